// round 3
// baseline (speedup 1.0000x reference)
#include <cuda_runtime.h>

// WeightedConvTranspose, parity-split form:
//   l=2p   : j=2t,   t=0..4, x index i = p+t-2
//   l=2p+1 : j=2t+1, t=0..3, x index i = p+t-1
// out[b,o,l] = sum_{c,taps} w[b,j,l] * x[b,c,i] * weight[o,c,j]
// w[b,j,l] = max(1 - ||coords[b,:,l+j-4] - coords[b,:,l]||/sigma, 0), 0 when i OOB.
//
// R2: register-block 2 pairs per thread (Np=2, No=8) to amortize weight LDS
// over 2x FMA work -> FMA-pipe bound instead of shared-memory bound.

#define B_      8
#define CIN_    64
#define COUT_   64
#define NIN_    16384
#define LOUT_   32768
#define KW_     9
#define PT_     128                 // output pairs per tile
#define XW_     (PT_ + 4)           // 132 x positions (halo 2 each side)
#define CSW_    (2 * PT_ + 8)       // 264 coords positions
#define THREADS_ 512
#define TILES_PER_B_ (NIN_ / PT_)   // 128
#define NTILES_ (B_ * TILES_PER_B_) // 1024

#define SMEM_W_FLOATS (CIN_ * KW_ * 64)   // 36864 (pitch 64, block-swizzled)
#define SMEM_X_FLOATS (CIN_ * XW_)        // 8448
#define SMEM_C_FLOATS (3 * CSW_)          // 792
#define SMEM_BYTES ((SMEM_W_FLOATS + SMEM_X_FLOATS + SMEM_C_FLOATS) * 4)  // ~184 KB

typedef unsigned long long ull;

static __device__ __forceinline__ ull pack2(float lo, float hi) {
    ull r;
    asm("mov.b64 %0, {%1, %2};" : "=l"(r) : "f"(lo), "f"(hi));
    return r;
}
static __device__ __forceinline__ void unpack2(ull v, float &lo, float &hi) {
    asm("mov.b64 {%0, %1}, %2;" : "=f"(lo), "=f"(hi) : "l"(v));
}
static __device__ __forceinline__ ull fma2(ull a, ull b, ull c) {
    ull d;
    asm("fma.rn.f32x2 %0, %1, %2, %3;" : "=l"(d) : "l"(a), "l"(b), "l"(c));
    return d;
}

__global__ void __launch_bounds__(THREADS_, 1)
wct_kernel(const float* __restrict__ x, const float* __restrict__ coords,
           const float* __restrict__ sigma, const float* __restrict__ weight,
           float* __restrict__ out) {
    extern __shared__ float smem[];
    float* w_s = smem;                      // [(c*9+j)*64 + swz(o,c)]
    float* x_s = smem + SMEM_W_FLOATS;      // [c][XW_]
    float* c_s = x_s + SMEM_X_FLOATS;       // [d][CSW_]

    const int tid = threadIdx.x;
    const int pg  = tid & 63;               // pair-group: handles pairs 2*pg, 2*pg+1
    const int og  = tid >> 6;               // o-group 0..7 (constant within warp)
    const int o8  = og * 8;

    // One-time weight transpose: gmem [o][c][j] -> smem [r=c*9+j][o] with a
    // per-c 16B-block rotation so STS conflicts are ~9-way (one-time) and
    // inner-loop reads stay 16B-contiguous.
    for (int idx = tid; idx < COUT_ * CIN_ * KW_; idx += THREADS_) {
        int o = idx / (CIN_ * KW_);
        int r = idx - o * (CIN_ * KW_);     // r = c*9 + j
        int c = r / KW_;
        int swz = ((((o >> 2) + c) & 15) << 2) + (o & 3);
        w_s[r * 64 + swz] = weight[idx];
    }

    const float rsig = 1.0f / sigma[0];

    for (int tile = blockIdx.x; tile < NTILES_; tile += gridDim.x) {
        __syncthreads();

        const int b  = tile / TILES_PER_B_;
        const int pt = tile - b * TILES_PER_B_;
        const int p0 = pt * PT_;

        // stage x slice [64][132]: x[b, c, p0-2+k]
        const float* xb = x + (size_t)b * (CIN_ * NIN_);
        for (int idx = tid; idx < SMEM_X_FLOATS; idx += THREADS_) {
            int c = idx / XW_;
            int k = idx - c * XW_;
            int g = p0 - 2 + k;
            x_s[idx] = ((unsigned)g < (unsigned)NIN_) ? xb[c * NIN_ + g] : 0.0f;
        }
        // stage coords slice [3][264]: coords[b, d, 2*p0-4+k]
        const float* cb = coords + (size_t)b * (3 * LOUT_);
        for (int idx = tid; idx < SMEM_C_FLOATS; idx += THREADS_) {
            int d = idx / CSW_;
            int k = idx - d * CSW_;
            int m = 2 * p0 - 4 + k;
            c_s[idx] = ((unsigned)m < (unsigned)LOUT_) ? cb[d * LOUT_ + m] : 0.0f;
        }
        __syncthreads();

        // per-thread radial window weights for 2 pairs
        float we0[5], we1[5], wo0[4], wo1[4];
        #pragma unroll
        for (int q = 0; q < 2; ++q) {
            const int pl = 2 * pg + q;
            const int p  = p0 + pl;
            const int kc = 2 * pl + 4;
            float cx = c_s[kc], cy = c_s[CSW_ + kc], cz = c_s[2 * CSW_ + kc];
            #pragma unroll
            for (int t = 0; t < 5; ++t) {
                int k = 2 * pl + 2 * t;
                float dx = c_s[k] - cx;
                float dy = c_s[CSW_ + k] - cy;
                float dz = c_s[2 * CSW_ + k] - cz;
                float nn = sqrtf(fmaf(dx, dx, fmaf(dy, dy, dz * dz)));
                float wv = fmaxf(1.0f - nn * rsig, 0.0f);
                wv = ((unsigned)(p + t - 2) < (unsigned)NIN_) ? wv : 0.0f;
                if (q == 0) we0[t] = wv; else we1[t] = wv;
            }
            const int ko = 2 * pl + 5;
            float ox = c_s[ko], oy = c_s[CSW_ + ko], oz = c_s[2 * CSW_ + ko];
            #pragma unroll
            for (int t = 0; t < 4; ++t) {
                int k = 2 * pl + 2 * t + 2;
                float dx = c_s[k] - ox;
                float dy = c_s[CSW_ + k] - oy;
                float dz = c_s[2 * CSW_ + k] - oz;
                float nn = sqrtf(fmaf(dx, dx, fmaf(dy, dy, dz * dz)));
                float wv = fmaxf(1.0f - nn * rsig, 0.0f);
                wv = ((unsigned)(p + t - 1) < (unsigned)NIN_) ? wv : 0.0f;
                if (q == 0) wo0[t] = wv; else wo1[t] = wv;
            }
        }

        // accumulators: 2 pairs x 8 outputs (even+odd), as f32x2 over outputs
        ull ae0[4] = {0,0,0,0}, ae1[4] = {0,0,0,0};
        ull ao0[4] = {0,0,0,0}, ao1[4] = {0,0,0,0};

        const float* xrow  = x_s + 2 * pg;
        const float* wbase = w_s;
        const int og2 = og << 1;

        #pragma unroll 2
        for (int c = 0; c < CIN_; ++c) {
            float2 x01 = *(const float2*)(xrow);
            float2 x23 = *(const float2*)(xrow + 2);
            float2 x45 = *(const float2*)(xrow + 4);
            float xv[6] = {x01.x, x01.y, x23.x, x23.y, x45.x, x45.y};

            const float* wp0 = wbase + (((og2     + c) & 15) << 2);
            const float* wp1 = wbase + (((og2 + 1 + c) & 15) << 2);

            #pragma unroll
            for (int t = 0; t < 5; ++t) {               // even taps j = 2t
                ulonglong2 wa = *(const ulonglong2*)(wp0 + (2 * t) * 64);
                ulonglong2 wb = *(const ulonglong2*)(wp1 + (2 * t) * 64);
                float s0 = we0[t] * xv[t];
                ull s02 = pack2(s0, s0);
                ae0[0] = fma2(s02, wa.x, ae0[0]);
                ae0[1] = fma2(s02, wa.y, ae0[1]);
                ae0[2] = fma2(s02, wb.x, ae0[2]);
                ae0[3] = fma2(s02, wb.y, ae0[3]);
                float s1 = we1[t] * xv[t + 1];
                ull s12 = pack2(s1, s1);
                ae1[0] = fma2(s12, wa.x, ae1[0]);
                ae1[1] = fma2(s12, wa.y, ae1[1]);
                ae1[2] = fma2(s12, wb.x, ae1[2]);
                ae1[3] = fma2(s12, wb.y, ae1[3]);
            }
            #pragma unroll
            for (int t = 0; t < 4; ++t) {               // odd taps j = 2t+1
                ulonglong2 wa = *(const ulonglong2*)(wp0 + (2 * t + 1) * 64);
                ulonglong2 wb = *(const ulonglong2*)(wp1 + (2 * t + 1) * 64);
                float s0 = wo0[t] * xv[t + 1];
                ull s02 = pack2(s0, s0);
                ao0[0] = fma2(s02, wa.x, ao0[0]);
                ao0[1] = fma2(s02, wa.y, ao0[1]);
                ao0[2] = fma2(s02, wb.x, ao0[2]);
                ao0[3] = fma2(s02, wb.y, ao0[3]);
                float s1 = wo1[t] * xv[t + 2];
                ull s12 = pack2(s1, s1);
                ao1[0] = fma2(s12, wa.x, ao1[0]);
                ao1[1] = fma2(s12, wa.y, ao1[1]);
                ao1[2] = fma2(s12, wb.x, ao1[2]);
                ao1[3] = fma2(s12, wb.y, ao1[3]);
            }
            xrow  += XW_;
            wbase += KW_ * 64;
        }

        // epilogue: per output one STG.128 covering l = 2*(p0+2pg) .. +3
        float E0[8], E1[8], O0[8], O1[8];
        #pragma unroll
        for (int k = 0; k < 4; ++k) {
            unpack2(ae0[k], E0[2 * k], E0[2 * k + 1]);
            unpack2(ae1[k], E1[2 * k], E1[2 * k + 1]);
            unpack2(ao0[k], O0[2 * k], O0[2 * k + 1]);
            unpack2(ao1[k], O1[2 * k], O1[2 * k + 1]);
        }
        float* ob = out + ((size_t)(b * COUT_ + o8)) * LOUT_
                        + 2 * (size_t)(p0 + 2 * pg);
        #pragma unroll
        for (int oo = 0; oo < 8; ++oo) {
            *reinterpret_cast<float4*>(ob + (size_t)oo * LOUT_) =
                make_float4(E0[oo], O0[oo], E1[oo], O1[oo]);
        }
    }
}

extern "C" void kernel_launch(void* const* d_in, const int* in_sizes, int n_in,
                              void* d_out, int out_size) {
    const float* x      = (const float*)d_in[0];
    const float* coords = (const float*)d_in[1];
    const float* sigma  = (const float*)d_in[2];
    const float* weight = (const float*)d_in[3];
    float* out = (float*)d_out;
    (void)in_sizes; (void)n_in; (void)out_size;

    cudaFuncSetAttribute(wct_kernel, cudaFuncAttributeMaxDynamicSharedMemorySize, SMEM_BYTES);

    int dev = 0, sms = 148;
    cudaGetDevice(&dev);
    cudaDeviceGetAttribute(&sms, cudaDevAttrMultiProcessorCount, dev);
    if (sms <= 0) sms = 148;

    wct_kernel<<<sms, THREADS_, SMEM_BYTES>>>(x, coords, sigma, weight, out);
}

// round 6
// speedup vs baseline: 1.1311x; 1.1311x over previous
#include <cuda_runtime.h>
#include <cuda_bf16.h>
#include <cstdint>

// WeightedConvTranspose via mma.sync (bf16 m16n8k16) GEMM, parity-decomposed.
//  l=2p+par, tap j=2t+par: out[b,o,l] += we[j,p] * x[b,c,p+t+par-2] * weight[o,c,j]
// Per tile: D[128p x 64o] += V_chunk[128p x 64c] * W_chunk[64o x 64c]^T, 9 chunks.
// fp32 -> bf16 hi/lo split on both operands; 3 products (hh+hl+lh); fp32 reg accum.
// B operand loaded with NON-trans ldmatrix: W smem rows are o, K (=c) contiguous,
// so non-trans fragments give pairs along K at fixed n — the m16n8k16 B layout.

#define B_       8
#define NIN_     16384
#define LOUT_    32768
#define PT_      128
#define THREADS_ 512
#define TILES_   (B_ * (NIN_ / PT_))   // 1024

#define XP_      66
#define CSP_     264

// ---- SMEM layout (bytes) ----
#define OFF_W    0                      // 9 chunks x (hi 8192 | lo 8192) = 147456
#define WCH_(j)  (OFF_W + (j) * 16384)
#define OFF_VHI  147456
#define OFF_VLO  163840
#define OFF_X    180224                 // 132*66*4 = 34848
#define OFF_CS   (OFF_X + 34848)        // 3*264*4  = 3168
#define OFF_WE   (OFF_CS + 3168)        // 9*128*4  = 4608
#define SMEM_BYTES (OFF_WE + 4608)      // 222848

static __device__ __forceinline__ uint32_t smem_u32(const void* p) {
    uint32_t a;
    asm("{ .reg .u64 t; cvta.to.shared.u64 t, %1; cvt.u32.u64 %0, t; }" : "=r"(a) : "l"(p));
    return a;
}
static __device__ __forceinline__ uint32_t swz128(uint32_t off) {
    return off ^ ((off >> 3) & 0x70);
}
// pack two fp32 -> bf16x2 word: low half = a, high half = b
static __device__ __forceinline__ uint32_t cvt_bf16x2(float a, float b) {
    uint32_t r;
    asm("cvt.rn.bf16x2.f32 %0, %1, %2;" : "=r"(r) : "f"(b), "f"(a));
    return r;
}
static __device__ __forceinline__ void ldsm_x4(uint32_t* r, uint32_t addr) {
    asm volatile("ldmatrix.sync.aligned.m8n8.x4.shared.b16 {%0,%1,%2,%3}, [%4];"
                 : "=r"(r[0]), "=r"(r[1]), "=r"(r[2]), "=r"(r[3]) : "r"(addr));
}
static __device__ __forceinline__ void mma_bf16(float* d, const uint32_t* a,
                                                uint32_t b0, uint32_t b1) {
    asm volatile("mma.sync.aligned.m16n8k16.row.col.f32.bf16.bf16.f32 "
                 "{%0,%1,%2,%3}, {%4,%5,%6,%7}, {%8,%9}, {%0,%1,%2,%3};"
                 : "+f"(d[0]), "+f"(d[1]), "+f"(d[2]), "+f"(d[3])
                 : "r"(a[0]), "r"(a[1]), "r"(a[2]), "r"(a[3]), "r"(b0), "r"(b1));
}

__global__ void __launch_bounds__(THREADS_, 1)
wct_mma_kernel(const float* __restrict__ x, const float* __restrict__ coords,
               const float* __restrict__ sigma, const float* __restrict__ weight,
               float* __restrict__ out) {
    extern __shared__ char smem[];
    const uint32_t sb = smem_u32(smem);
    const int tid  = threadIdx.x;
    const int wid  = tid >> 5;
    const int lane = tid & 31;

    float* x_s  = (float*)(smem + OFF_X);
    float* cs_s = (float*)(smem + OFF_CS);
    float* we_s = (float*)(smem + OFF_WE);

    // ---- one-time W hi/lo split: chunk j = W[o][c] for tap j, SW128 rows of 128B ----
    for (int idx = tid; idx < 64 * 64 * 9; idx += THREADS_) {
        int j  = idx % 9;
        int oc = idx / 9;                    // oc = o*64 + c
        int c  = oc & 63;
        int o  = oc >> 6;
        float w = weight[oc * 9 + j];
        __nv_bfloat16 hb = __float2bfloat16(w);
        float hf = __bfloat162float(hb);
        __nv_bfloat16 lb = __float2bfloat16(w - hf);
        uint32_t bo = swz128((uint32_t)o * 128 + (uint32_t)c * 2);
        *(__nv_bfloat16*)(smem + WCH_(j) + bo)        = hb;
        *(__nv_bfloat16*)(smem + WCH_(j) + 8192 + bo) = lb;
    }
    const float rsig = 1.0f / sigma[0];

    // warp tile: 16 warps = 8 p-groups x 2 o-groups; each 16p x 32o
    const int pg = wid >> 1, og = wid & 1;
    const int pbase = pg * 16;
    // A (V) ldmatrix: lanes 0-15 -> rows m0-15 (k0-7), lanes 16-31 -> same rows, k8-15
    const uint32_t a_ro = (uint32_t)(pbase + (lane & 15)) * 128 + (uint32_t)(lane >> 4) * 16;
    // B (W) ldmatrix non-trans: 8 o-rows, lanes {0-7,8-15,16-23,24-31} at c-offsets {0,8,16,24}
    const uint32_t b_lane_col = (uint32_t)(lane >> 3) * 16;   // bytes within half-row
    const uint32_t b_row      = (uint32_t)(og * 32 + (lane & 7));
    // V build lane mapping
    const int bp  = wid * 8 + (lane >> 2);
    const int bc0 = lane & 3;

    __syncthreads();  // W ready

    for (int ti = blockIdx.x; ti < TILES_; ti += gridDim.x) {
        const int b  = ti >> 7;
        const int p0 = (ti & 127) * PT_;

        // stage x slice: x_s[xi][c], g = p0 - 2 + xi, zero-padded
        for (int idx = tid; idx < 132 * 64; idx += THREADS_) {
            int c  = idx / 132;
            int xi = idx - c * 132;
            int g  = p0 - 2 + xi;
            x_s[xi * XP_ + c] =
                ((unsigned)g < (unsigned)NIN_) ? x[((size_t)b * 64 + c) * NIN_ + g] : 0.0f;
        }
        // stage coords: cs[d][k], g = 2*p0 - 4 + k
        for (int idx = tid; idx < 3 * CSP_; idx += THREADS_) {
            int d = idx / CSP_;
            int k = idx - d * CSP_;
            int g = 2 * p0 - 4 + k;
            cs_s[idx] = ((unsigned)g < (unsigned)LOUT_)
                      ? coords[((size_t)b * 3 + d) * LOUT_ + g] : 0.0f;
        }
        __syncthreads();

        // radial weights we[j][p] for l = 2p + (j&1)
        for (int idx = tid; idx < 9 * 128; idx += THREADS_) {
            int j = idx >> 7;
            int p = idx & 127;
            int par = j & 1;
            int kt = 2 * p + par + j;
            int kc = 2 * p + par + 4;
            float dx = cs_s[kt] - cs_s[kc];
            float dy = cs_s[CSP_ + kt] - cs_s[CSP_ + kc];
            float dz = cs_s[2 * CSP_ + kt] - cs_s[2 * CSP_ + kc];
            float nn = sqrtf(fmaf(dx, dx, fmaf(dy, dy, dz * dz)));
            we_s[idx] = fmaxf(1.0f - nn * rsig, 0.0f);
        }
        __syncthreads();

        float acc_e[16], acc_o[16];
        #pragma unroll
        for (int i = 0; i < 16; ++i) { acc_e[i] = 0.0f; acc_o[i] = 0.0f; }

        // ---- chunk loop: 9 taps, each K=64 ----
        #pragma unroll 1
        for (int j = 0; j < 9; ++j) {
            const int par  = j & 1;
            const int toff = (j >> 1) + par;     // xi = p + toff

            // build V chunk (bf16 hi/lo, SW128 rows of 128B)
            {
                const float wt = we_s[j * 128 + bp];
                const float* xr = x_s + (bp + toff) * XP_;
                #pragma unroll
                for (int rr = 0; rr < 8; ++rr) {
                    int cw = bc0 + rr * 4;
                    float2 xv = *(const float2*)(xr + 2 * cw);
                    float v0 = wt * xv.x;
                    float v1 = wt * xv.y;
                    uint32_t hi = cvt_bf16x2(v0, v1);
                    float h0 = __uint_as_float(hi << 16);
                    float h1 = __uint_as_float(hi & 0xffff0000u);
                    uint32_t lo = cvt_bf16x2(v0 - h0, v1 - h1);
                    uint32_t bo = swz128((uint32_t)bp * 128 + (uint32_t)cw * 4);
                    *(uint32_t*)(smem + OFF_VHI + bo) = hi;
                    *(uint32_t*)(smem + OFF_VLO + bo) = lo;
                }
            }
            __syncthreads();  // V visible

            float* acc = par ? acc_o : acc_e;
            const uint32_t wch = sb + (uint32_t)WCH_(j);

            // B fragments: [jn][k16] -> (b0,b1); one ldsm.x4 covers 2 k16 steps
            uint32_t Bh[4][4], Bl[4][4];   // [jn][2*half + reg] regs r0..r3 per half loaded pairwise
            #pragma unroll
            for (int jn = 0; jn < 4; ++jn) {
                #pragma unroll
                for (int half = 0; half < 2; ++half) {
                    uint32_t ro = (b_row + (uint32_t)jn * 8) * 128
                                + (uint32_t)half * 64 + b_lane_col;
                    uint32_t r[4];
                    ldsm_x4(r, wch + swz128(ro));
                    Bh[jn][2 * half + 0] = r[0];  // b0 of k16 = 2*half
                    Bh[jn][2 * half + 1] = r[1];  // b1 of k16 = 2*half
                    // stash k16 = 2*half+1 regs in Bl temporarily? no — need r2,r3 too.
                    // Use Bl for lo-matrix; keep r2,r3 of hi in separate array below.
                    (void)r;
                    // store r2,r3 for the odd k16 step:
                    Bl[jn][2 * half + 0] = r[2];
                    Bl[jn][2 * half + 1] = r[3];
                }
            }
            // Bh[jn][{0,1}] = k16 0 (b0,b1) of half0; Bh[jn][{2,3}] = k16 2 (half1)
            // Bl[jn][{0,1}] = k16 1 (half0 r2,r3);   Bl[jn][{2,3}] = k16 3 (half1)
            // lo-split W fragments loaded per k16 below (8 more ldsm)

            #pragma unroll
            for (int k16 = 0; k16 < 4; ++k16) {
                const uint32_t kb = (uint32_t)k16 * 32;
                uint32_t ah[4], al[4];
                ldsm_x4(ah, sb + OFF_VHI + swz128(a_ro + kb));
                ldsm_x4(al, sb + OFF_VLO + swz128(a_ro + kb));
                const int half = k16 >> 1, odd = k16 & 1;
                #pragma unroll
                for (int jn = 0; jn < 4; ++jn) {
                    uint32_t b0h, b1h;
                    if (!odd) { b0h = Bh[jn][2 * half]; b1h = Bh[jn][2 * half + 1]; }
                    else      { b0h = Bl[jn][2 * half]; b1h = Bl[jn][2 * half + 1]; }
                    mma_bf16(acc + 4 * jn, ah, b0h, b1h);   // hh
                    mma_bf16(acc + 4 * jn, al, b0h, b1h);   // lh
                }
                // hl: lo-W fragments for this k16 (one ldsm.x4 serves 2 jn groups)
                #pragma unroll
                for (int jp = 0; jp < 2; ++jp) {
                    // load 16 o-rows (2 jn groups) x 16 c for this k16:
                    // lanes 0-15 -> rows, c-offset kb; lanes 16-31 -> same rows, kb+16
                    uint32_t ro = (b_row % 8 + (uint32_t)(og * 32 + jp * 16) + ((lane >> 3) & 1) * 8) * 128;
                    // recompute cleanly: rows r = og*32 + jp*16 + (lane&15 mapped to 16 rows)
                    ro = (uint32_t)(og * 32 + jp * 16 + (lane & 15)) * 128
                       + kb + (uint32_t)(lane >> 4) * 16;
                    uint32_t r[4];
                    ldsm_x4(r, wch + 8192 + swz128(ro));
                    // matrices: m0 = rows jp*16+0..7 (k lo 8), m1 = rows +8..15,
                    //           m2 = rows 0..7 (k hi 8),      m3 = rows +8..15
                    mma_bf16(acc + 4 * (2 * jp + 0), ah, r[0], r[2]);  // hl
                    mma_bf16(acc + 4 * (2 * jp + 1), ah, r[1], r[3]);  // hl
                }
            }
            __syncthreads();  // reads done before next build overwrites V
        }

        // ---- epilogue: float2 (even, odd) per (o, p) ----
        {
            float* obB = out + (size_t)b * 64 * LOUT_;
            #pragma unroll
            for (int jn = 0; jn < 4; ++jn) {
                #pragma unroll
                for (int e = 0; e < 2; ++e) {
                    int o  = og * 32 + jn * 8 + (lane & 3) * 2 + e;
                    int p1 = pbase + (lane >> 2);
                    float* orow = obB + (size_t)o * LOUT_;
                    *(float2*)(orow + 2 * (size_t)(p0 + p1)) =
                        make_float2(acc_e[4 * jn + e], acc_o[4 * jn + e]);
                    *(float2*)(orow + 2 * (size_t)(p0 + p1 + 8)) =
                        make_float2(acc_e[4 * jn + 2 + e], acc_o[4 * jn + 2 + e]);
                }
            }
        }
        __syncthreads();
    }
}

extern "C" void kernel_launch(void* const* d_in, const int* in_sizes, int n_in,
                              void* d_out, int out_size) {
    const float* x      = (const float*)d_in[0];
    const float* coords = (const float*)d_in[1];
    const float* sigma  = (const float*)d_in[2];
    const float* weight = (const float*)d_in[3];
    float* out = (float*)d_out;
    (void)in_sizes; (void)n_in; (void)out_size;

    cudaFuncSetAttribute(wct_mma_kernel, cudaFuncAttributeMaxDynamicSharedMemorySize, SMEM_BYTES);

    int dev = 0, sms = 148;
    cudaGetDevice(&dev);
    cudaDeviceGetAttribute(&sms, cudaDevAttrMultiProcessorCount, dev);
    if (sms <= 0) sms = 148;

    wct_mma_kernel<<<sms, THREADS_, SMEM_BYTES>>>(x, coords, sigma, weight, out);
}

// round 7
// speedup vs baseline: 1.9245x; 1.7015x over previous
#include <cuda_runtime.h>
#include <cuda_bf16.h>
#include <cstdint>

// WeightedConvTranspose via mma.sync (bf16 m16n8k16), parity-decomposed.
// R7: tap-independent X hi/lo bf16 operand built ONCE per tile; radial weight
// we[j,p] applied as fp32 scalar on per-chunk accumulator. No syncs in chunk loop.

#define B_       8
#define NIN_     16384
#define LOUT_    32768
#define PT_      128
#define THREADS_ 512
#define TILES_   (B_ * (NIN_ / PT_))   // 1024

#define XP_      66
#define CSP_     264

// ---- SMEM layout (bytes) ----
#define OFF_W    0                      // 9 chunks x (hi 8192 | lo 8192) = 147456
#define WCH_(j)  (OFF_W + (j) * 16384)
#define OFF_XHI  147456                 // 132 rows x 128B = 16896
#define OFF_XLO  (OFF_XHI + 16896)      // 164352
#define OFF_X    (OFF_XLO + 16896)      // 181248: fp32 stage 132*66*4 = 34848
#define OFF_CS   (OFF_X + 34848)        // 216096: 3*264*4 = 3168
#define OFF_WE   (OFF_CS + 3168)        // 219264: 9*128*4 = 4608
#define SMEM_BYTES (OFF_WE + 4608)      // 223872

static __device__ __forceinline__ uint32_t smem_u32(const void* p) {
    uint32_t a;
    asm("{ .reg .u64 t; cvta.to.shared.u64 t, %1; cvt.u32.u64 %0, t; }" : "=r"(a) : "l"(p));
    return a;
}
static __device__ __forceinline__ uint32_t swz128(uint32_t off) {
    return off ^ ((off >> 3) & 0x70);
}
// pack two fp32 -> bf16x2 word: low half = a, high half = b
static __device__ __forceinline__ uint32_t cvt_bf16x2(float a, float b) {
    uint32_t r;
    asm("cvt.rn.bf16x2.f32 %0, %1, %2;" : "=r"(r) : "f"(b), "f"(a));
    return r;
}
static __device__ __forceinline__ void ldsm_x4(uint32_t* r, uint32_t addr) {
    asm volatile("ldmatrix.sync.aligned.m8n8.x4.shared.b16 {%0,%1,%2,%3}, [%4];"
                 : "=r"(r[0]), "=r"(r[1]), "=r"(r[2]), "=r"(r[3]) : "r"(addr));
}
static __device__ __forceinline__ void mma_bf16(float* d, const uint32_t* a,
                                                uint32_t b0, uint32_t b1) {
    asm volatile("mma.sync.aligned.m16n8k16.row.col.f32.bf16.bf16.f32 "
                 "{%0,%1,%2,%3}, {%4,%5,%6,%7}, {%8,%9}, {%0,%1,%2,%3};"
                 : "+f"(d[0]), "+f"(d[1]), "+f"(d[2]), "+f"(d[3])
                 : "r"(a[0]), "r"(a[1]), "r"(a[2]), "r"(a[3]), "r"(b0), "r"(b1));
}

__global__ void __launch_bounds__(THREADS_, 1)
wct_mma_kernel(const float* __restrict__ x, const float* __restrict__ coords,
               const float* __restrict__ sigma, const float* __restrict__ weight,
               float* __restrict__ out) {
    extern __shared__ char smem[];
    const uint32_t sb = smem_u32(smem);
    const int tid  = threadIdx.x;
    const int wid  = tid >> 5;
    const int lane = tid & 31;

    float* x_s  = (float*)(smem + OFF_X);
    float* cs_s = (float*)(smem + OFF_CS);
    float* we_s = (float*)(smem + OFF_WE);

    // ---- one-time W hi/lo split: chunk j = W[o][c] for tap j, SW128 rows of 128B ----
    for (int idx = tid; idx < 64 * 64 * 9; idx += THREADS_) {
        int j  = idx % 9;
        int oc = idx / 9;                    // oc = o*64 + c
        int c  = oc & 63;
        int o  = oc >> 6;
        float w = weight[oc * 9 + j];
        __nv_bfloat16 hb = __float2bfloat16(w);
        float hf = __bfloat162float(hb);
        __nv_bfloat16 lb = __float2bfloat16(w - hf);
        uint32_t bo = swz128((uint32_t)o * 128 + (uint32_t)c * 2);
        *(__nv_bfloat16*)(smem + WCH_(j) + bo)        = hb;
        *(__nv_bfloat16*)(smem + WCH_(j) + 8192 + bo) = lb;
    }
    const float rsig = 1.0f / sigma[0];

    // warp tile: 16 warps = 8 p-groups x 2 o-groups; each 16p x 32o
    const int pg = wid >> 1, og = wid & 1;
    const int pbase = pg * 16;
    // A ldsm: lanes 0-15 -> rows (k0-7), lanes 16-31 -> same rows (k8-15)
    const uint32_t a_ro = (uint32_t)(pbase + (lane & 15)) * 128 + (uint32_t)(lane >> 4) * 16;
    // B ldsm (16-row form): rows = og*32 + jp*16 + (lane&15), col half by lane>>4
    const uint32_t b_ro0 = (uint32_t)(og * 32 + 0  + (lane & 15)) * 128 + (uint32_t)(lane >> 4) * 16;
    const uint32_t b_ro1 = (uint32_t)(og * 32 + 16 + (lane & 15)) * 128 + (uint32_t)(lane >> 4) * 16;
    // X convert mapping: 4 lanes per row, rows 0..127; tail rows 128..131 by tid<64
    const int bp  = wid * 8 + (lane >> 2);
    const int bc0 = lane & 3;

    __syncthreads();  // W ready

    for (int ti = blockIdx.x; ti < TILES_; ti += gridDim.x) {
        const int b  = ti >> 7;
        const int p0 = (ti & 127) * PT_;

        // ---- phase 1: stage x (fp32) + coords, coalesced ----
        for (int idx = tid; idx < 132 * 64; idx += THREADS_) {
            int c  = idx / 132;
            int xi = idx - c * 132;
            int g  = p0 - 2 + xi;
            x_s[xi * XP_ + c] =
                ((unsigned)g < (unsigned)NIN_) ? x[((size_t)b * 64 + c) * NIN_ + g] : 0.0f;
        }
        for (int idx = tid; idx < 3 * CSP_; idx += THREADS_) {
            int d = idx / CSP_;
            int k = idx - d * CSP_;
            int g = 2 * p0 - 4 + k;
            cs_s[idx] = ((unsigned)g < (unsigned)LOUT_)
                      ? coords[((size_t)b * 3 + d) * LOUT_ + g] : 0.0f;
        }
        __syncthreads();

        // ---- phase 2: convert x -> X hi/lo bf16 (SW128 rows), compute we ----
        {
            const float* xr = x_s + bp * XP_;
            const uint32_t m = ((uint32_t)bp & 7) << 4;
            char* hbase = smem + OFF_XHI + bp * 128;
            char* lbase = smem + OFF_XLO + bp * 128;
            #pragma unroll
            for (int rr = 0; rr < 4; ++rr) {
                int fo = bc0 * 4 + rr * 16;           // 4 floats (c = fo..fo+3)
                float2 v01 = *(const float2*)(xr + fo);
                float2 v23 = *(const float2*)(xr + fo + 2);
                uint32_t h0 = cvt_bf16x2(v01.x, v01.y);
                uint32_t h1 = cvt_bf16x2(v23.x, v23.y);
                uint32_t l0 = cvt_bf16x2(v01.x - __uint_as_float(h0 << 16),
                                         v01.y - __uint_as_float(h0 & 0xffff0000u));
                uint32_t l1 = cvt_bf16x2(v23.x - __uint_as_float(h1 << 16),
                                         v23.y - __uint_as_float(h1 & 0xffff0000u));
                uint32_t d = ((uint32_t)fo * 2) ^ m;  // 8B-aligned (mask hits bits 4-6)
                *(uint2*)(hbase + d) = make_uint2(h0, h1);
                *(uint2*)(lbase + d) = make_uint2(l0, l1);
            }
            if (tid < 64) {                            // tail rows 128..131
                int row = 128 + (tid >> 4);
                int fo  = (tid & 15) * 4;
                const float* xr2 = x_s + row * XP_;
                const uint32_t m2 = ((uint32_t)row & 7) << 4;
                float2 v01 = *(const float2*)(xr2 + fo);
                float2 v23 = *(const float2*)(xr2 + fo + 2);
                uint32_t h0 = cvt_bf16x2(v01.x, v01.y);
                uint32_t h1 = cvt_bf16x2(v23.x, v23.y);
                uint32_t l0 = cvt_bf16x2(v01.x - __uint_as_float(h0 << 16),
                                         v01.y - __uint_as_float(h0 & 0xffff0000u));
                uint32_t l1 = cvt_bf16x2(v23.x - __uint_as_float(h1 << 16),
                                         v23.y - __uint_as_float(h1 & 0xffff0000u));
                uint32_t d = ((uint32_t)fo * 2) ^ m2;
                *(uint2*)(smem + OFF_XHI + row * 128 + d) = make_uint2(h0, h1);
                *(uint2*)(smem + OFF_XLO + row * 128 + d) = make_uint2(l0, l1);
            }
        }
        // radial weights we[j][p] for l = 2p + (j&1)
        for (int idx = tid; idx < 9 * 128; idx += THREADS_) {
            int j = idx >> 7;
            int p = idx & 127;
            int par = j & 1;
            int kt = 2 * p + par + j;
            int kc = 2 * p + par + 4;
            float dx = cs_s[kt] - cs_s[kc];
            float dy = cs_s[CSP_ + kt] - cs_s[CSP_ + kc];
            float dz = cs_s[2 * CSP_ + kt] - cs_s[2 * CSP_ + kc];
            float nn = sqrtf(fmaf(dx, dx, fmaf(dy, dy, dz * dz)));
            we_s[idx] = fmaxf(1.0f - nn * rsig, 0.0f);
        }
        __syncthreads();

        // ---- phase 3: chunk loop, sync-free (all SMEM operands read-only) ----
        float acc_e[16], acc_o[16];
        #pragma unroll
        for (int i = 0; i < 16; ++i) { acc_e[i] = 0.0f; acc_o[i] = 0.0f; }

        const uint32_t xhi_b = sb + OFF_XHI;
        const uint32_t xlo_b = sb + OFF_XLO;
        const int prow = pbase + (lane >> 2);

        #pragma unroll 1
        for (int j = 0; j < 9; ++j) {
            const int toff = (j >> 1) + (j & 1);
            const uint32_t wch = sb + (uint32_t)WCH_(j);
            const uint32_t aro = a_ro + (uint32_t)toff * 128;

            float tmp[16];
            #pragma unroll
            for (int i = 0; i < 16; ++i) tmp[i] = 0.0f;

            #pragma unroll
            for (int k16 = 0; k16 < 4; ++k16) {
                const uint32_t kb = (uint32_t)k16 * 32;
                uint32_t ah[4], al[4];
                ldsm_x4(ah, xhi_b + swz128(aro + kb));
                ldsm_x4(al, xlo_b + swz128(aro + kb));
                {
                    uint32_t rh[4], rl[4];
                    ldsm_x4(rh, wch + swz128(b_ro0 + kb));
                    ldsm_x4(rl, wch + 8192 + swz128(b_ro0 + kb));
                    mma_bf16(tmp + 0, ah, rh[0], rh[2]);
                    mma_bf16(tmp + 4, ah, rh[1], rh[3]);
                    mma_bf16(tmp + 0, al, rh[0], rh[2]);
                    mma_bf16(tmp + 4, al, rh[1], rh[3]);
                    mma_bf16(tmp + 0, ah, rl[0], rl[2]);
                    mma_bf16(tmp + 4, ah, rl[1], rl[3]);
                }
                {
                    uint32_t rh[4], rl[4];
                    ldsm_x4(rh, wch + swz128(b_ro1 + kb));
                    ldsm_x4(rl, wch + 8192 + swz128(b_ro1 + kb));
                    mma_bf16(tmp + 8,  ah, rh[0], rh[2]);
                    mma_bf16(tmp + 12, ah, rh[1], rh[3]);
                    mma_bf16(tmp + 8,  al, rh[0], rh[2]);
                    mma_bf16(tmp + 12, al, rh[1], rh[3]);
                    mma_bf16(tmp + 8,  ah, rl[0], rl[2]);
                    mma_bf16(tmp + 12, ah, rl[1], rl[3]);
                }
            }
            // scale by we[j, prow(+8)] and accumulate
            const float w0 = we_s[j * 128 + prow];
            const float w1 = we_s[j * 128 + prow + 8];
            float* acc = (j & 1) ? acc_o : acc_e;
            #pragma unroll
            for (int i = 0; i < 16; ++i) {
                const float w = (i & 2) ? w1 : w0;
                acc[i] = fmaf(w, tmp[i], acc[i]);
            }
        }

        // ---- epilogue: float2 (even, odd) per (o, p) ----
        {
            float* obB = out + (size_t)b * 64 * LOUT_;
            #pragma unroll
            for (int jn = 0; jn < 4; ++jn) {
                #pragma unroll
                for (int e = 0; e < 2; ++e) {
                    int o = og * 32 + jn * 8 + (lane & 3) * 2 + e;
                    float* orow = obB + (size_t)o * LOUT_;
                    *(float2*)(orow + 2 * (size_t)(p0 + prow)) =
                        make_float2(acc_e[4 * jn + e], acc_o[4 * jn + e]);
                    *(float2*)(orow + 2 * (size_t)(p0 + prow + 8)) =
                        make_float2(acc_e[4 * jn + 2 + e], acc_o[4 * jn + 2 + e]);
                }
            }
        }
        __syncthreads();  // x_s / XHI / we_s reuse next tile
    }
}

extern "C" void kernel_launch(void* const* d_in, const int* in_sizes, int n_in,
                              void* d_out, int out_size) {
    const float* x      = (const float*)d_in[0];
    const float* coords = (const float*)d_in[1];
    const float* sigma  = (const float*)d_in[2];
    const float* weight = (const float*)d_in[3];
    float* out = (float*)d_out;
    (void)in_sizes; (void)n_in; (void)out_size;

    cudaFuncSetAttribute(wct_mma_kernel, cudaFuncAttributeMaxDynamicSharedMemorySize, SMEM_BYTES);

    int dev = 0, sms = 148;
    cudaGetDevice(&dev);
    cudaDeviceGetAttribute(&sms, cudaDevAttrMultiProcessorCount, dev);
    if (sms <= 0) sms = 148;

    wct_mma_kernel<<<sms, THREADS_, SMEM_BYTES>>>(x, coords, sigma, weight, out);
}